// round 5
// baseline (speedup 1.0000x reference)
#include <cuda_runtime.h>
#include <math_constants.h>

#define NGRAPH 1024
#define D      256
#define NITERS 6

// ---------------- device scratch (no allocations allowed) ----------------
__device__ __align__(16) float g_h[NGRAPH * D];
__device__ __align__(16) float g_c[NGRAPH * D];
__device__ __align__(16) float g_qstar[NGRAPH * 2 * D];
__device__ __align__(16) float g_gates[NGRAPH * 4 * D];
__device__ int g_segoff[NGRAPH + 1];

// ---------------- segment offsets via binary search ----------------
__global__ void seg_offsets_kernel(const int* __restrict__ seg, int N) {
    int b = blockIdx.x * blockDim.x + threadIdx.x;
    if (b > NGRAPH) return;
    int lo = 0, hi = N;
    while (lo < hi) {
        int mid = (lo + hi) >> 1;
        if (seg[mid] < b) lo = mid + 1; else hi = mid;
    }
    g_segoff[b] = lo;
}

__global__ void init_zero_kernel() {
    int i = blockIdx.x * blockDim.x + threadIdx.x;
    if (i < NGRAPH * D) { g_h[i] = 0.f; g_c[i] = 0.f; }
    if (i < NGRAPH * 2 * D) g_qstar[i] = 0.f;
}

// ---------------- generic NT GEMM tile body ----------------
// C[M,N] = A1[M,K1] @ B1[N,K1]^T (+ A2[M,K2] @ B2[N,K2]^T) + bias1 (+ bias2)
// BM=BN=64, BK=16, 256 threads, 4x4 outputs per thread.
template <bool TWO>
__device__ __forceinline__ void gemm_body(
    const float* __restrict__ A1, int K1, const float* __restrict__ B1,
    const float* __restrict__ A2, int K2, const float* __restrict__ B2,
    const float* __restrict__ bias1, const float* __restrict__ bias2,
    float* __restrict__ C, int N)
{
    const int BM = 64, BN = 64, BK = 16;
    __shared__ float As[BK][BM];
    __shared__ float Bs[BK][BN];

    int tid = threadIdx.x;
    int tx = tid & 15;        // col group
    int ty = tid >> 4;        // row group
    int row0 = blockIdx.y * BM;
    int col0 = blockIdx.x * BN;

    float acc[4][4];
#pragma unroll
    for (int i = 0; i < 4; i++)
#pragma unroll
        for (int j = 0; j < 4; j++) acc[i][j] = 0.f;

    int lr = tid >> 2;          // 0..63 load row
    int lc = (tid & 3) * 4;     // 0,4,8,12 k offset

    const int nphase = TWO ? 2 : 1;
    for (int phase = 0; phase < nphase; phase++) {
        const float* A = (phase == 0) ? A1 : A2;
        const float* Bw = (phase == 0) ? B1 : B2;
        int K = (phase == 0) ? K1 : K2;
        for (int k0 = 0; k0 < K; k0 += BK) {
            float4 av = *(const float4*)(A + (size_t)(row0 + lr) * K + k0 + lc);
            float4 bv = *(const float4*)(Bw + (size_t)(col0 + lr) * K + k0 + lc);
            As[lc + 0][lr] = av.x; As[lc + 1][lr] = av.y;
            As[lc + 2][lr] = av.z; As[lc + 3][lr] = av.w;
            Bs[lc + 0][lr] = bv.x; Bs[lc + 1][lr] = bv.y;
            Bs[lc + 2][lr] = bv.z; Bs[lc + 3][lr] = bv.w;
            __syncthreads();
#pragma unroll
            for (int k = 0; k < BK; k++) {
                float a[4], b[4];
#pragma unroll
                for (int i = 0; i < 4; i++) a[i] = As[k][ty * 4 + i];
#pragma unroll
                for (int j = 0; j < 4; j++) b[j] = Bs[k][tx * 4 + j];
#pragma unroll
                for (int i = 0; i < 4; i++)
#pragma unroll
                    for (int j = 0; j < 4; j++) acc[i][j] += a[i] * b[j];
            }
            __syncthreads();
        }
    }

#pragma unroll
    for (int j = 0; j < 4; j++) {
        int col = col0 + tx * 4 + j;
        float bias = bias1[col] + (TWO ? bias2[col] : 0.f);
#pragma unroll
        for (int i = 0; i < 4; i++) {
            int row = row0 + ty * 4 + i;
            C[(size_t)row * N + col] = acc[i][j] + bias;
        }
    }
}

// gates = qstar @ W_ih^T + h @ W_hh^T + b_ih + b_hh    [1024 x 1024]
__global__ void __launch_bounds__(256)
gemm_gates_kernel(const float* __restrict__ W_ih, const float* __restrict__ W_hh,
                  const float* __restrict__ b_ih, const float* __restrict__ b_hh)
{
    gemm_body<true>(g_qstar, 2 * D, W_ih, g_h, D, W_hh, b_ih, b_hh, g_gates, 4 * D);
}

// out = qstar @ fc_w^T + fc_b    [1024 x 256]
__global__ void __launch_bounds__(256)
gemm_out_kernel(const float* __restrict__ fc_w, const float* __restrict__ fc_b,
                float* __restrict__ out)
{
    gemm_body<false>(g_qstar, 2 * D, fc_w, (const float*)nullptr, 0,
                     (const float*)nullptr, fc_b, (const float*)nullptr, out, D);
}

// ---------------- fused LSTM-elementwise + attention + readout ----------------
// 1 block per graph, 8 warps. All device-global state referenced from DEVICE
// code only (never passed from host).
__global__ void __launch_bounds__(256)
attn_kernel(const float* __restrict__ feat)
{
    int b = blockIdx.x;
    int tid = threadIdx.x;
    int w = tid >> 5;
    int lane = tid & 31;

    __shared__ float q_sm[D];

    // ---- LSTM elementwise for graph b (gate order i, f, g, o) ----
    {
        const float* g = g_gates + (size_t)b * 4 * D;
        int d = tid;
        float gi = g[d];
        float gf = g[D + d];
        float gg = g[2 * D + d];
        float go = g[3 * D + d];
        float si = 1.f / (1.f + __expf(-gi));
        float sf = 1.f / (1.f + __expf(-gf));
        float so = 1.f / (1.f + __expf(-go));
        float c = sf * g_c[(size_t)b * D + d] + si * tanhf(gg);
        float h = so * tanhf(c);
        g_c[(size_t)b * D + d] = c;
        g_h[(size_t)b * D + d] = h;      // next iteration's GEMM input
        q_sm[d] = h;
    }
    __syncthreads();

    int start = g_segoff[b];
    int end = g_segoff[b + 1];

    float4 qa = *(const float4*)(q_sm + lane * 4);
    float4 qb = *(const float4*)(q_sm + 128 + lane * 4);

    float m = -CUDART_INF_F, s = 0.f;
    float4 ra = make_float4(0.f, 0.f, 0.f, 0.f);
    float4 rb = make_float4(0.f, 0.f, 0.f, 0.f);

    for (int n = start + w; n < end; n += 8) {
        const float4* fp = (const float4*)(feat + (size_t)n * D);
        float4 fa = fp[lane];
        float4 fb = fp[32 + lane];
        float p = fa.x * qa.x + fa.y * qa.y + fa.z * qa.z + fa.w * qa.w
                + fb.x * qb.x + fb.y * qb.y + fb.z * qb.z + fb.w * qb.w;
#pragma unroll
        for (int o = 16; o; o >>= 1) p += __shfl_xor_sync(0xffffffffu, p, o);

        float wgt;
        if (p > m) {
            float sc = __expf(m - p);   // first node: exp(-inf) = +0
            s *= sc;
            ra.x *= sc; ra.y *= sc; ra.z *= sc; ra.w *= sc;
            rb.x *= sc; rb.y *= sc; rb.z *= sc; rb.w *= sc;
            m = p;
            wgt = 1.f;
        } else {
            wgt = __expf(p - m);
        }
        s += wgt;
        ra.x += wgt * fa.x; ra.y += wgt * fa.y; ra.z += wgt * fa.z; ra.w += wgt * fa.w;
        rb.x += wgt * fb.x; rb.y += wgt * fb.y; rb.z += wgt * fb.z; rb.w += wgt * fb.w;
    }

    // cross-warp merge
    __shared__ float sm_m[8], sm_s[8];
    __shared__ float4 sm_ra[8][32];
    __shared__ float4 sm_rb[8][32];
    if (lane == 0) { sm_m[w] = m; sm_s[w] = s; }
    sm_ra[w][lane] = ra;
    sm_rb[w][lane] = rb;
    __syncthreads();

    int d = tid;  // output dim 0..255
    float M = -CUDART_INF_F;
#pragma unroll
    for (int i = 0; i < 8; i++) M = fmaxf(M, sm_m[i]);

    float out = 0.f;
    if (M > -CUDART_INF_F) {
        const float* base = (d < 128) ? ((const float*)sm_ra) + d
                                      : ((const float*)sm_rb) + (d - 128);
        float S = 0.f, R = 0.f;
#pragma unroll
        for (int i = 0; i < 8; i++) {
            float sc = __expf(sm_m[i] - M);
            S += sm_s[i] * sc;
            R += base[i * 128] * sc;
        }
        if (S > 0.f) out = R / S;
    }
    g_qstar[(size_t)b * 2 * D + D + d] = out;     // readout half
    g_qstar[(size_t)b * 2 * D + d] = q_sm[d];     // q half
}

// ---------------- launch ----------------
extern "C" void kernel_launch(void* const* d_in, const int* in_sizes, int n_in,
                              void* d_out, int out_size)
{
    // bind by size (all distinct; the two 1024-elem biases only appear summed)
    const float *feat = 0, *W_ih = 0, *W_hh = 0, *fc_w = 0, *fc_b = 0;
    const float *b_1 = 0, *b_2 = 0;
    const int* seg = 0;

    int fi = 0;
    long long best = -1;
    for (int i = 0; i < n_in; i++)
        if ((long long)in_sizes[i] > best) { best = in_sizes[i]; fi = i; }
    feat = (const float*)d_in[fi];
    int N = in_sizes[fi] / D;

    for (int i = 0; i < n_in; i++) {
        if (i == fi) continue;
        int s = in_sizes[i];
        if      (s == 4 * D * 2 * D) W_ih = (const float*)d_in[i];
        else if (s == 4 * D * D)     W_hh = (const float*)d_in[i];
        else if (s == D * 2 * D)     fc_w = (const float*)d_in[i];
        else if (s == 4 * D)         { if (!b_1) b_1 = (const float*)d_in[i];
                                       else      b_2 = (const float*)d_in[i]; }
        else if (s == D)             fc_b = (const float*)d_in[i];
        else if (s == N)             seg  = (const int*)d_in[i];
    }
    float* out = (float*)d_out;

    seg_offsets_kernel<<<(NGRAPH + 1 + 255) / 256, 256>>>(seg, N);
    init_zero_kernel<<<(NGRAPH * 2 * D + 255) / 256, 256>>>();

    dim3 gGates(1024 / 64, 1024 / 64);
    dim3 gOut(256 / 64, 1024 / 64);

    for (int it = 0; it < NITERS; it++) {
        gemm_gates_kernel<<<gGates, 256>>>(W_ih, W_hh, b_1, b_2);
        attn_kernel<<<NGRAPH, 256>>>(feat);
    }
    gemm_out_kernel<<<gOut, 256>>>(fc_w, fc_b, out);
}

// round 6
// speedup vs baseline: 1.6621x; 1.6621x over previous
#include <cuda_runtime.h>
#include <math_constants.h>

#define NGRAPH 1024
#define D      256
#define NITERS 6
#define NSPLIT 4

// ---------------- device scratch ----------------
__device__ __align__(16) float g_h[NGRAPH * D];
__device__ __align__(16) float g_read[NGRAPH * D];
__device__ __align__(16) float g_c[2][NGRAPH * D];          // ping-pong
__device__ __align__(16) float g_gates[NGRAPH * 4 * D];
__device__ __align__(16) float g_Wc[4 * D * D];             // W_ih[:, :256] + W_hh
__device__ __align__(16) float g_Wr[4 * D * D];             // W_ih[:, 256:]
__device__ __align__(16) float g_pm[NGRAPH * NSPLIT];
__device__ __align__(16) float g_ps[NGRAPH * NSPLIT];
__device__ __align__(16) float g_pr[NGRAPH * NSPLIT * D];
__device__ int g_segoff[NGRAPH + 1];

// ---------------- segment offsets ----------------
__global__ void seg_offsets_kernel(const int* __restrict__ seg, int N) {
    int b = blockIdx.x * blockDim.x + threadIdx.x;
    if (b > NGRAPH) return;
    int lo = 0, hi = N;
    while (lo < hi) {
        int mid = (lo + hi) >> 1;
        if (seg[mid] < b) lo = mid + 1; else hi = mid;
    }
    g_segoff[b] = lo;
}

__global__ void init_zero_kernel() {
    int i = blockIdx.x * blockDim.x + threadIdx.x;
    if (i < NGRAPH * D) { g_h[i] = 0.f; g_read[i] = 0.f; g_c[0][i] = 0.f; }
}

// Wc = W_ih[:, :D] + W_hh ; Wr = W_ih[:, D:2D]  (both compact [4D, D])
__global__ void prep_w_kernel(const float* __restrict__ W_ih,
                              const float* __restrict__ W_hh) {
    int i = blockIdx.x * blockDim.x + threadIdx.x;
    if (i >= 4 * D * D) return;
    int row = i >> 8, col = i & 255;
    g_Wc[i] = W_ih[(size_t)row * 2 * D + col] + W_hh[i];
    g_Wr[i] = W_ih[(size_t)row * 2 * D + D + col];
}

// ---------------- double-buffered NT GEMM ----------------
// C[M x N] = A1[M,256] @ B1[N,256(ldB1)]^T + A2[M,256] @ B2[N,256(ldB2)]^T + bias
// BM=BN=64, BK=16, 256 threads, 4x4 per thread.
__device__ __forceinline__ void gemm2(
    const float* __restrict__ A1, int ldA1, const float* __restrict__ B1, int ldB1,
    const float* __restrict__ A2, int ldA2, const float* __restrict__ B2, int ldB2,
    const float* __restrict__ bias1, const float* __restrict__ bias2,
    float* __restrict__ C, int ldC)
{
    const int BM = 64, BN = 64, BK = 16, KH = D, T = (2 * D) / BK;  // 32 chunks
    __shared__ float As[2][BK][BM];
    __shared__ float Bs[2][BK][BN];

    int tid = threadIdx.x;
    int tx = tid & 15, ty = tid >> 4;
    int row0 = blockIdx.y * BM, col0 = blockIdx.x * BN;
    int lr = tid >> 2, lc = (tid & 3) * 4;

    float acc[4][4];
#pragma unroll
    for (int i = 0; i < 4; i++)
#pragma unroll
        for (int j = 0; j < 4; j++) acc[i][j] = 0.f;

    auto ldgA = [&](int t) -> float4 {
        int kk = t * BK + lc;
        return (kk < KH)
            ? *(const float4*)(A1 + (size_t)(row0 + lr) * ldA1 + kk)
            : *(const float4*)(A2 + (size_t)(row0 + lr) * ldA2 + (kk - KH));
    };
    auto ldgB = [&](int t) -> float4 {
        int kk = t * BK + lc;
        return (kk < KH)
            ? *(const float4*)(B1 + (size_t)(col0 + lr) * ldB1 + kk)
            : *(const float4*)(B2 + (size_t)(col0 + lr) * ldB2 + (kk - KH));
    };
    auto sts = [&](int buf, float4 av, float4 bv) {
        As[buf][lc + 0][lr] = av.x; As[buf][lc + 1][lr] = av.y;
        As[buf][lc + 2][lr] = av.z; As[buf][lc + 3][lr] = av.w;
        Bs[buf][lc + 0][lr] = bv.x; Bs[buf][lc + 1][lr] = bv.y;
        Bs[buf][lc + 2][lr] = bv.z; Bs[buf][lc + 3][lr] = bv.w;
    };

    {
        float4 av = ldgA(0), bv = ldgB(0);
        sts(0, av, bv);
    }
    __syncthreads();

    for (int t = 0; t < T; t++) {
        float4 av, bv;
        if (t + 1 < T) { av = ldgA(t + 1); bv = ldgB(t + 1); }
        int cur = t & 1;
#pragma unroll
        for (int k = 0; k < BK; k++) {
            float a[4], b[4];
#pragma unroll
            for (int i = 0; i < 4; i++) a[i] = As[cur][k][ty * 4 + i];
#pragma unroll
            for (int j = 0; j < 4; j++) b[j] = Bs[cur][k][tx * 4 + j];
#pragma unroll
            for (int i = 0; i < 4; i++)
#pragma unroll
                for (int j = 0; j < 4; j++) acc[i][j] += a[i] * b[j];
        }
        if (t + 1 < T) sts(cur ^ 1, av, bv);
        __syncthreads();
    }

#pragma unroll
    for (int j = 0; j < 4; j++) {
        int col = col0 + tx * 4 + j;
        float bias = bias1[col] + (bias2 ? bias2[col] : 0.f);
#pragma unroll
        for (int i = 0; i < 4; i++) {
            int row = row0 + ty * 4 + i;
            C[(size_t)row * ldC + col] = acc[i][j] + bias;
        }
    }
}

// gates = h @ Wc^T + readout @ Wr^T + (b_ih + b_hh)
__global__ void __launch_bounds__(256)
gemm_gates_kernel(const float* __restrict__ b1, const float* __restrict__ b2)
{
    gemm2(g_h, D, g_Wc, D, g_read, D, g_Wr, D, b1, b2, g_gates, 4 * D);
}

// out = h @ fc_w[:, :256]^T + readout @ fc_w[:, 256:]^T + fc_b
__global__ void __launch_bounds__(256)
gemm_fc_kernel(const float* __restrict__ fc_w, const float* __restrict__ fc_b,
               float* __restrict__ out)
{
    gemm2(g_h, D, fc_w, 2 * D, g_read, D, fc_w + D, 2 * D,
          fc_b, (const float*)nullptr, out, D);
}

// ---------------- fused LSTM + attention phase-1 (4 splits/segment) ----------------
__global__ void __launch_bounds__(256)
attn_phase1_kernel(const float* __restrict__ feat, int parity)
{
    int u = blockIdx.x;            // 0..4095
    int b = u >> 2, sp = u & 3;
    int tid = threadIdx.x;
    int w = tid >> 5, lane = tid & 31;

    __shared__ float q_sm[D];

    // ---- LSTM elementwise for graph b (redundant across the 4 split blocks;
    //      safe: c ping-pong, identical writes) ----
    {
        const float* g = g_gates + (size_t)b * 4 * D;
        int d = tid;
        float gi = g[d];
        float gf = g[D + d];
        float gg = g[2 * D + d];
        float go = g[3 * D + d];
        float si = 1.f / (1.f + __expf(-gi));
        float sf = 1.f / (1.f + __expf(-gf));
        float so = 1.f / (1.f + __expf(-go));
        float c = sf * g_c[parity][(size_t)b * D + d] + si * tanhf(gg);
        float h = so * tanhf(c);
        g_c[parity ^ 1][(size_t)b * D + d] = c;
        g_h[(size_t)b * D + d] = h;
        q_sm[d] = h;
    }
    __syncthreads();

    int start = g_segoff[b];
    int end = g_segoff[b + 1];

    float4 qa = *(const float4*)(q_sm + lane * 4);
    float4 qb = *(const float4*)(q_sm + 128 + lane * 4);

    float m = -CUDART_INF_F, s = 0.f;
    float4 ra = make_float4(0.f, 0.f, 0.f, 0.f);
    float4 rb = make_float4(0.f, 0.f, 0.f, 0.f);

    for (int n = start + sp * 8 + w; n < end; n += 32) {
        const float4* fp = (const float4*)(feat + (size_t)n * D);
        float4 fa = fp[lane];
        float4 fb = fp[32 + lane];
        float p = fa.x * qa.x + fa.y * qa.y + fa.z * qa.z + fa.w * qa.w
                + fb.x * qb.x + fb.y * qb.y + fb.z * qb.z + fb.w * qb.w;
#pragma unroll
        for (int o = 16; o; o >>= 1) p += __shfl_xor_sync(0xffffffffu, p, o);

        float wgt;
        if (p > m) {
            float sc = __expf(m - p);       // first node: exp(-inf) = +0
            s *= sc;
            ra.x *= sc; ra.y *= sc; ra.z *= sc; ra.w *= sc;
            rb.x *= sc; rb.y *= sc; rb.z *= sc; rb.w *= sc;
            m = p;
            wgt = 1.f;
        } else {
            wgt = __expf(p - m);
        }
        s += wgt;
        ra.x += wgt * fa.x; ra.y += wgt * fa.y; ra.z += wgt * fa.z; ra.w += wgt * fa.w;
        rb.x += wgt * fb.x; rb.y += wgt * fb.y; rb.z += wgt * fb.z; rb.w += wgt * fb.w;
    }

    // cross-warp merge -> block partial (m, s, r[256]) unnormalized
    __shared__ float sm_m[8], sm_s[8];
    __shared__ float4 sm_ra[8][32];
    __shared__ float4 sm_rb[8][32];
    if (lane == 0) { sm_m[w] = m; sm_s[w] = s; }
    sm_ra[w][lane] = ra;
    sm_rb[w][lane] = rb;
    __syncthreads();

    int d = tid;
    float M = -CUDART_INF_F;
#pragma unroll
    for (int i = 0; i < 8; i++) M = fmaxf(M, sm_m[i]);

    float S = 0.f, R = 0.f;
    if (M > -CUDART_INF_F) {
        const float* base = (d < 128) ? ((const float*)sm_ra) + d
                                      : ((const float*)sm_rb) + (d - 128);
#pragma unroll
        for (int i = 0; i < 8; i++) {
            float sc = __expf(sm_m[i] - M);
            S += sm_s[i] * sc;
            R += base[i * 128] * sc;
        }
    }
    g_pr[(size_t)u * D + d] = R;
    if (tid == 0) { g_pm[u] = M; g_ps[u] = S; }
}

// ---------------- merge 4 partials per graph ----------------
__global__ void __launch_bounds__(256)
attn_merge_kernel()
{
    int b = blockIdx.x;
    int d = threadIdx.x;
    float m0 = g_pm[b * 4 + 0], m1 = g_pm[b * 4 + 1];
    float m2 = g_pm[b * 4 + 2], m3 = g_pm[b * 4 + 3];
    float M = fmaxf(fmaxf(m0, m1), fmaxf(m2, m3));
    float out = 0.f;
    if (M > -CUDART_INF_F) {
        float e0 = __expf(m0 - M), e1 = __expf(m1 - M);
        float e2 = __expf(m2 - M), e3 = __expf(m3 - M);
        float S = g_ps[b * 4 + 0] * e0 + g_ps[b * 4 + 1] * e1
                + g_ps[b * 4 + 2] * e2 + g_ps[b * 4 + 3] * e3;
        float R = g_pr[(size_t)(b * 4 + 0) * D + d] * e0
                + g_pr[(size_t)(b * 4 + 1) * D + d] * e1
                + g_pr[(size_t)(b * 4 + 2) * D + d] * e2
                + g_pr[(size_t)(b * 4 + 3) * D + d] * e3;
        if (S > 0.f) out = R / S;
    }
    g_read[(size_t)b * D + d] = out;
}

// ---------------- launch ----------------
extern "C" void kernel_launch(void* const* d_in, const int* in_sizes, int n_in,
                              void* d_out, int out_size)
{
    // bind by size (all distinct; the two 1024-elem biases only appear summed)
    const float *feat = 0, *W_ih = 0, *W_hh = 0, *fc_w = 0, *fc_b = 0;
    const float *b_1 = 0, *b_2 = 0;
    const int* seg = 0;

    int fi = 0;
    long long best = -1;
    for (int i = 0; i < n_in; i++)
        if ((long long)in_sizes[i] > best) { best = in_sizes[i]; fi = i; }
    feat = (const float*)d_in[fi];
    int N = in_sizes[fi] / D;

    for (int i = 0; i < n_in; i++) {
        if (i == fi) continue;
        int s = in_sizes[i];
        if      (s == 4 * D * 2 * D) W_ih = (const float*)d_in[i];
        else if (s == 4 * D * D)     W_hh = (const float*)d_in[i];
        else if (s == D * 2 * D)     fc_w = (const float*)d_in[i];
        else if (s == 4 * D)         { if (!b_1) b_1 = (const float*)d_in[i];
                                       else      b_2 = (const float*)d_in[i]; }
        else if (s == D)             fc_b = (const float*)d_in[i];
        else if (s == N)             seg  = (const int*)d_in[i];
    }
    float* out = (float*)d_out;

    seg_offsets_kernel<<<(NGRAPH + 1 + 255) / 256, 256>>>(seg, N);
    init_zero_kernel<<<(NGRAPH * D + 255) / 256, 256>>>();
    prep_w_kernel<<<(4 * D * D + 255) / 256, 256>>>(W_ih, W_hh);

    dim3 gGates(4 * D / 64, NGRAPH / 64);   // (16, 16)
    dim3 gFc(D / 64, NGRAPH / 64);          // (4, 16)

    for (int it = 0; it < NITERS; it++) {
        gemm_gates_kernel<<<gGates, 256>>>(b_1, b_2);
        attn_phase1_kernel<<<NGRAPH * NSPLIT, 256>>>(feat, it & 1);
        attn_merge_kernel<<<NGRAPH, 256>>>();
    }
    gemm_fc_kernel<<<gFc, 256>>>(fc_w, fc_b, out);
}

// round 7
// speedup vs baseline: 1.8564x; 1.1169x over previous
#include <cuda_runtime.h>
#include <cuda_fp16.h>
#include <math_constants.h>

#define NGRAPH 1024
#define D      256
#define NITERS 6
#define NSPLIT 4
#define MAXN   400000

// ---------------- device scratch ----------------
__device__ __align__(16) float g_h[NGRAPH * D];
__device__ __align__(16) float g_read[NGRAPH * D];
__device__ __align__(16) float g_c[2][NGRAPH * D];          // ping-pong
__device__ __align__(16) float g_gates[NGRAPH * 4 * D];
__device__ __align__(16) float g_Wc[4 * D * D];             // W_ih[:, :256] + W_hh
__device__ __align__(16) float g_Wr[4 * D * D];             // W_ih[:, 256:]
__device__ __align__(16) float g_pm[NGRAPH * NSPLIT];
__device__ __align__(16) float g_ps[NGRAPH * NSPLIT];
__device__ __align__(16) float g_pr[NGRAPH * NSPLIT * D];
__device__ __align__(16) __half g_feat16[(size_t)MAXN * D]; // fp16 feat copy
__device__ int g_segoff[NGRAPH + 1];

// ---------------- segment offsets ----------------
__global__ void seg_offsets_kernel(const int* __restrict__ seg, int N) {
    int b = blockIdx.x * blockDim.x + threadIdx.x;
    if (b > NGRAPH) return;
    int lo = 0, hi = N;
    while (lo < hi) {
        int mid = (lo + hi) >> 1;
        if (seg[mid] < b) lo = mid + 1; else hi = mid;
    }
    g_segoff[b] = lo;
}

__global__ void init_zero_kernel() {
    int i = blockIdx.x * blockDim.x + threadIdx.x;
    if (i < NGRAPH * D) { g_h[i] = 0.f; g_read[i] = 0.f; g_c[0][i] = 0.f; }
}

// Wc = W_ih[:, :D] + W_hh ; Wr = W_ih[:, D:2D]  (both compact [4D, D])
__global__ void prep_w_kernel(const float* __restrict__ W_ih,
                              const float* __restrict__ W_hh) {
    int i = blockIdx.x * blockDim.x + threadIdx.x;
    if (i >= 4 * D * D) return;
    int row = i >> 8, col = i & 255;
    g_Wc[i] = W_ih[(size_t)row * 2 * D + col] + W_hh[i];
    g_Wr[i] = W_ih[(size_t)row * 2 * D + D + col];
}

// ---------------- 128x64 double-buffered NT GEMM (gates) ----------------
// C[1024 x 1024] = h[1024,256] @ Wc[1024,256]^T + read[1024,256] @ Wr[1024,256]^T + b1+b2
// BM=128, BN=64, BK=16, 256 threads, 8x4 per thread. grid=(16,8)=128 blocks.
__global__ void __launch_bounds__(256)
gemm_gates_kernel(const float* __restrict__ b1, const float* __restrict__ b2)
{
    const int BK = 16, T = 32;   // 32 chunks over K=512 (two 256 halves)
    __shared__ float As[2][BK][128];
    __shared__ float Bs[2][BK][64];

    int tid = threadIdx.x;
    int tx = tid & 15, ty = tid >> 4;
    int row0 = blockIdx.y * 128, col0 = blockIdx.x * 64;
    int lr = tid >> 2, lc = (tid & 3) * 4;

    float acc[8][4];
#pragma unroll
    for (int i = 0; i < 8; i++)
#pragma unroll
        for (int j = 0; j < 4; j++) acc[i][j] = 0.f;

    auto ldgA = [&](int t, float4& a0, float4& a1) {
        int kk = t * BK + lc;
        const float* A  = (kk < D) ? g_h : g_read;
        int k            = (kk < D) ? kk : kk - D;
        a0 = *(const float4*)(A + (size_t)(row0 + lr) * D + k);
        a1 = *(const float4*)(A + (size_t)(row0 + lr + 64) * D + k);
    };
    auto ldgB = [&](int t) -> float4 {
        int kk = t * BK + lc;
        const float* B = (kk < D) ? g_Wc : g_Wr;
        int k           = (kk < D) ? kk : kk - D;
        return *(const float4*)(B + (size_t)(col0 + lr) * D + k);
    };
    auto sts = [&](int buf, float4 a0, float4 a1, float4 bv) {
        As[buf][lc + 0][lr] = a0.x; As[buf][lc + 1][lr] = a0.y;
        As[buf][lc + 2][lr] = a0.z; As[buf][lc + 3][lr] = a0.w;
        As[buf][lc + 0][lr + 64] = a1.x; As[buf][lc + 1][lr + 64] = a1.y;
        As[buf][lc + 2][lr + 64] = a1.z; As[buf][lc + 3][lr + 64] = a1.w;
        Bs[buf][lc + 0][lr] = bv.x; Bs[buf][lc + 1][lr] = bv.y;
        Bs[buf][lc + 2][lr] = bv.z; Bs[buf][lc + 3][lr] = bv.w;
    };

    {
        float4 a0, a1, bv = ldgB(0);
        ldgA(0, a0, a1);
        sts(0, a0, a1, bv);
    }
    __syncthreads();

    for (int t = 0; t < T; t++) {
        float4 a0, a1, bv;
        if (t + 1 < T) { ldgA(t + 1, a0, a1); bv = ldgB(t + 1); }
        int cur = t & 1;
#pragma unroll
        for (int k = 0; k < BK; k++) {
            float a[8], b[4];
#pragma unroll
            for (int i = 0; i < 8; i++) a[i] = As[cur][k][ty * 8 + i];
#pragma unroll
            for (int j = 0; j < 4; j++) b[j] = Bs[cur][k][tx * 4 + j];
#pragma unroll
            for (int i = 0; i < 8; i++)
#pragma unroll
                for (int j = 0; j < 4; j++) acc[i][j] += a[i] * b[j];
        }
        if (t + 1 < T) sts(cur ^ 1, a0, a1, bv);
        __syncthreads();
    }

#pragma unroll
    for (int j = 0; j < 4; j++) {
        int col = col0 + tx * 4 + j;
        float bias = b1[col] + b2[col];
#pragma unroll
        for (int i = 0; i < 8; i++) {
            int row = row0 + ty * 8 + i;
            g_gates[(size_t)row * 4 * D + col] = acc[i][j] + bias;
        }
    }
}

// ---------------- 64x64 double-buffered NT GEMM (fc, runs once) ----------------
__global__ void __launch_bounds__(256)
gemm_fc_kernel(const float* __restrict__ fc_w, const float* __restrict__ fc_b,
               float* __restrict__ out)
{
    const int BK = 16, T = 32;
    __shared__ float As[2][BK][64];
    __shared__ float Bs[2][BK][64];

    int tid = threadIdx.x;
    int tx = tid & 15, ty = tid >> 4;
    int row0 = blockIdx.y * 64, col0 = blockIdx.x * 64;
    int lr = tid >> 2, lc = (tid & 3) * 4;

    float acc[4][4];
#pragma unroll
    for (int i = 0; i < 4; i++)
#pragma unroll
        for (int j = 0; j < 4; j++) acc[i][j] = 0.f;

    auto ldgA = [&](int t) -> float4 {
        int kk = t * BK + lc;
        const float* A = (kk < D) ? g_h : g_read;
        int k           = (kk < D) ? kk : kk - D;
        return *(const float4*)(A + (size_t)(row0 + lr) * D + k);
    };
    auto ldgB = [&](int t) -> float4 {
        int kk = t * BK + lc;   // fc_w is [D, 2D]; col maj split at D
        return *(const float4*)(fc_w + (size_t)(col0 + lr) * 2 * D + kk);
    };
    auto sts = [&](int buf, float4 av, float4 bv) {
        As[buf][lc + 0][lr] = av.x; As[buf][lc + 1][lr] = av.y;
        As[buf][lc + 2][lr] = av.z; As[buf][lc + 3][lr] = av.w;
        Bs[buf][lc + 0][lr] = bv.x; Bs[buf][lc + 1][lr] = bv.y;
        Bs[buf][lc + 2][lr] = bv.z; Bs[buf][lc + 3][lr] = bv.w;
    };

    { float4 av = ldgA(0), bv = ldgB(0); sts(0, av, bv); }
    __syncthreads();

    for (int t = 0; t < T; t++) {
        float4 av, bv;
        if (t + 1 < T) { av = ldgA(t + 1); bv = ldgB(t + 1); }
        int cur = t & 1;
#pragma unroll
        for (int k = 0; k < BK; k++) {
            float a[4], b[4];
#pragma unroll
            for (int i = 0; i < 4; i++) a[i] = As[cur][k][ty * 4 + i];
#pragma unroll
            for (int j = 0; j < 4; j++) b[j] = Bs[cur][k][tx * 4 + j];
#pragma unroll
            for (int i = 0; i < 4; i++)
#pragma unroll
                for (int j = 0; j < 4; j++) acc[i][j] += a[i] * b[j];
        }
        if (t + 1 < T) sts(cur ^ 1, av, bv);
        __syncthreads();
    }

#pragma unroll
    for (int j = 0; j < 4; j++) {
        int col = col0 + tx * 4 + j;
        float bias = fc_b[col];
#pragma unroll
        for (int i = 0; i < 4; i++) {
            int row = row0 + ty * 4 + i;
            out[(size_t)row * D + col] = acc[i][j] + bias;
        }
    }
}

// ---------------- shared LSTM-elementwise helper ----------------
__device__ __forceinline__ void lstm_elem(int b, int parity, float* q_sm) {
    const float* g = g_gates + (size_t)b * 4 * D;
    int d = threadIdx.x;
    float gi = g[d];
    float gf = g[D + d];
    float gg = g[2 * D + d];
    float go = g[3 * D + d];
    float si = 1.f / (1.f + __expf(-gi));
    float sf = 1.f / (1.f + __expf(-gf));
    float so = 1.f / (1.f + __expf(-go));
    float c = sf * g_c[parity][(size_t)b * D + d] + si * tanhf(gg);
    float h = so * tanhf(c);
    g_c[parity ^ 1][(size_t)b * D + d] = c;
    g_h[(size_t)b * D + d] = h;
    q_sm[d] = h;
}

// ---------------- iter-1: fp32 attention + fp16 conversion write ----------------
__global__ void __launch_bounds__(256)
attn_phase1_f32_kernel(const float* __restrict__ feat, int parity)
{
    int u = blockIdx.x;            // 0..4095
    int b = u >> 2, sp = u & 3;
    int tid = threadIdx.x;
    int w = tid >> 5, lane = tid & 31;

    __shared__ float q_sm[D];
    lstm_elem(b, parity, q_sm);
    __syncthreads();

    int start = g_segoff[b];
    int end = g_segoff[b + 1];

    float4 qa = *(const float4*)(q_sm + lane * 4);
    float4 qb = *(const float4*)(q_sm + 128 + lane * 4);

    float m = -CUDART_INF_F, s = 0.f;
    float4 ra = make_float4(0.f, 0.f, 0.f, 0.f);
    float4 rb = make_float4(0.f, 0.f, 0.f, 0.f);

    for (int n = start + sp * 8 + w; n < end; n += 32) {
        const float4* fp = (const float4*)(feat + (size_t)n * D);
        float4 fa = fp[lane];
        float4 fb = fp[32 + lane];

        // write fp16 copy (each node visited by exactly one block/warp)
        __half* row16 = g_feat16 + (size_t)n * D;
        __half2 ha0 = __float22half2_rn(make_float2(fa.x, fa.y));
        __half2 ha1 = __float22half2_rn(make_float2(fa.z, fa.w));
        __half2 hb0 = __float22half2_rn(make_float2(fb.x, fb.y));
        __half2 hb1 = __float22half2_rn(make_float2(fb.z, fb.w));
        ((__half2*)row16)[lane * 2 + 0] = ha0;
        ((__half2*)row16)[lane * 2 + 1] = ha1;
        ((__half2*)(row16 + 128))[lane * 2 + 0] = hb0;
        ((__half2*)(row16 + 128))[lane * 2 + 1] = hb1;

        float p = fa.x * qa.x + fa.y * qa.y + fa.z * qa.z + fa.w * qa.w
                + fb.x * qb.x + fb.y * qb.y + fb.z * qb.z + fb.w * qb.w;
#pragma unroll
        for (int o = 16; o; o >>= 1) p += __shfl_xor_sync(0xffffffffu, p, o);

        float wgt;
        if (p > m) {
            float sc = __expf(m - p);
            s *= sc;
            ra.x *= sc; ra.y *= sc; ra.z *= sc; ra.w *= sc;
            rb.x *= sc; rb.y *= sc; rb.z *= sc; rb.w *= sc;
            m = p; wgt = 1.f;
        } else {
            wgt = __expf(p - m);
        }
        s += wgt;
        ra.x += wgt * fa.x; ra.y += wgt * fa.y; ra.z += wgt * fa.z; ra.w += wgt * fa.w;
        rb.x += wgt * fb.x; rb.y += wgt * fb.y; rb.z += wgt * fb.z; rb.w += wgt * fb.w;
    }

    // cross-warp merge (lane owns dims 4l..4l+3 / 128+4l..)
    __shared__ float sm_m[8], sm_s[8];
    __shared__ float4 sm_ra[8][32];
    __shared__ float4 sm_rb[8][32];
    if (lane == 0) { sm_m[w] = m; sm_s[w] = s; }
    sm_ra[w][lane] = ra;
    sm_rb[w][lane] = rb;
    __syncthreads();

    int d = tid;
    float M = -CUDART_INF_F;
#pragma unroll
    for (int i = 0; i < 8; i++) M = fmaxf(M, sm_m[i]);

    float S = 0.f, R = 0.f;
    if (M > -CUDART_INF_F) {
        const float* base = (d < 128) ? ((const float*)sm_ra) + d
                                      : ((const float*)sm_rb) + (d - 128);
#pragma unroll
        for (int i = 0; i < 8; i++) {
            float sc = __expf(sm_m[i] - M);
            S += sm_s[i] * sc;
            R += base[i * 128] * sc;
        }
    }
    g_pr[(size_t)u * D + d] = R;
    if (tid == 0) { g_pm[u] = M; g_ps[u] = S; }
}

// ---------------- iters 2..6: fp16 attention ----------------
__global__ void __launch_bounds__(256)
attn_phase1_f16_kernel(int parity)
{
    int u = blockIdx.x;
    int b = u >> 2, sp = u & 3;
    int tid = threadIdx.x;
    int w = tid >> 5, lane = tid & 31;

    __shared__ float q_sm[D];
    lstm_elem(b, parity, q_sm);
    __syncthreads();

    int start = g_segoff[b];
    int end = g_segoff[b + 1];

    // lane owns dims 8l .. 8l+7
    float qv[8];
#pragma unroll
    for (int i = 0; i < 8; i++) qv[i] = q_sm[lane * 8 + i];

    float m = -CUDART_INF_F, s = 0.f;
    float r[8];
#pragma unroll
    for (int i = 0; i < 8; i++) r[i] = 0.f;

    for (int n = start + sp * 8 + w; n < end; n += 32) {
        const uint4* rp = (const uint4*)(g_feat16 + (size_t)n * D);
        uint4 v = rp[lane];
        __half2 h0 = *(__half2*)&v.x;
        __half2 h1 = *(__half2*)&v.y;
        __half2 h2 = *(__half2*)&v.z;
        __half2 h3 = *(__half2*)&v.w;
        float2 f0 = __half22float2(h0);
        float2 f1 = __half22float2(h1);
        float2 f2 = __half22float2(h2);
        float2 f3 = __half22float2(h3);
        float f[8] = { f0.x, f0.y, f1.x, f1.y, f2.x, f2.y, f3.x, f3.y };

        float p = 0.f;
#pragma unroll
        for (int i = 0; i < 8; i++) p += f[i] * qv[i];
#pragma unroll
        for (int o = 16; o; o >>= 1) p += __shfl_xor_sync(0xffffffffu, p, o);

        float wgt;
        if (p > m) {
            float sc = __expf(m - p);
            s *= sc;
#pragma unroll
            for (int i = 0; i < 8; i++) r[i] *= sc;
            m = p; wgt = 1.f;
        } else {
            wgt = __expf(p - m);
        }
        s += wgt;
#pragma unroll
        for (int i = 0; i < 8; i++) r[i] += wgt * f[i];
    }

    // cross-warp merge: sm_r[w][dim]
    __shared__ float sm_m[8], sm_s[8];
    __shared__ float sm_r[8][D];
    if (lane == 0) { sm_m[w] = m; sm_s[w] = s; }
    *(float4*)&sm_r[w][lane * 8 + 0] = make_float4(r[0], r[1], r[2], r[3]);
    *(float4*)&sm_r[w][lane * 8 + 4] = make_float4(r[4], r[5], r[6], r[7]);
    __syncthreads();

    int d = tid;
    float M = -CUDART_INF_F;
#pragma unroll
    for (int i = 0; i < 8; i++) M = fmaxf(M, sm_m[i]);

    float S = 0.f, R = 0.f;
    if (M > -CUDART_INF_F) {
#pragma unroll
        for (int i = 0; i < 8; i++) {
            float sc = __expf(sm_m[i] - M);
            S += sm_s[i] * sc;
            R += sm_r[i][d] * sc;
        }
    }
    g_pr[(size_t)u * D + d] = R;
    if (tid == 0) { g_pm[u] = M; g_ps[u] = S; }
}

// ---------------- merge 4 partials per graph ----------------
__global__ void __launch_bounds__(256)
attn_merge_kernel()
{
    int b = blockIdx.x;
    int d = threadIdx.x;
    float m0 = g_pm[b * 4 + 0], m1 = g_pm[b * 4 + 1];
    float m2 = g_pm[b * 4 + 2], m3 = g_pm[b * 4 + 3];
    float M = fmaxf(fmaxf(m0, m1), fmaxf(m2, m3));
    float out = 0.f;
    if (M > -CUDART_INF_F) {
        float e0 = __expf(m0 - M), e1 = __expf(m1 - M);
        float e2 = __expf(m2 - M), e3 = __expf(m3 - M);
        float S = g_ps[b * 4 + 0] * e0 + g_ps[b * 4 + 1] * e1
                + g_ps[b * 4 + 2] * e2 + g_ps[b * 4 + 3] * e3;
        float R = g_pr[(size_t)(b * 4 + 0) * D + d] * e0
                + g_pr[(size_t)(b * 4 + 1) * D + d] * e1
                + g_pr[(size_t)(b * 4 + 2) * D + d] * e2
                + g_pr[(size_t)(b * 4 + 3) * D + d] * e3;
        if (S > 0.f) out = R / S;
    }
    g_read[(size_t)b * D + d] = out;
}

// ---------------- launch ----------------
extern "C" void kernel_launch(void* const* d_in, const int* in_sizes, int n_in,
                              void* d_out, int out_size)
{
    const float *feat = 0, *W_ih = 0, *W_hh = 0, *fc_w = 0, *fc_b = 0;
    const float *b_1 = 0, *b_2 = 0;
    const int* seg = 0;

    int fi = 0;
    long long best = -1;
    for (int i = 0; i < n_in; i++)
        if ((long long)in_sizes[i] > best) { best = in_sizes[i]; fi = i; }
    feat = (const float*)d_in[fi];
    int N = in_sizes[fi] / D;

    for (int i = 0; i < n_in; i++) {
        if (i == fi) continue;
        int s = in_sizes[i];
        if      (s == 4 * D * 2 * D) W_ih = (const float*)d_in[i];
        else if (s == 4 * D * D)     W_hh = (const float*)d_in[i];
        else if (s == D * 2 * D)     fc_w = (const float*)d_in[i];
        else if (s == 4 * D)         { if (!b_1) b_1 = (const float*)d_in[i];
                                       else      b_2 = (const float*)d_in[i]; }
        else if (s == D)             fc_b = (const float*)d_in[i];
        else if (s == N)             seg  = (const int*)d_in[i];
    }
    float* out = (float*)d_out;

    seg_offsets_kernel<<<(NGRAPH + 1 + 255) / 256, 256>>>(seg, N);
    init_zero_kernel<<<(NGRAPH * D + 255) / 256, 256>>>();
    prep_w_kernel<<<(4 * D * D + 255) / 256, 256>>>(W_ih, W_hh);

    dim3 gGates(4 * D / 64, NGRAPH / 128);   // (16, 8) = 128 blocks
    dim3 gFc(D / 64, NGRAPH / 64);           // (4, 16)

    for (int it = 0; it < NITERS; it++) {
        gemm_gates_kernel<<<gGates, 256>>>(b_1, b_2);
        if (it == 0)
            attn_phase1_f32_kernel<<<NGRAPH * NSPLIT, 256>>>(feat, 0);
        else
            attn_phase1_f16_kernel<<<NGRAPH * NSPLIT, 256>>>(it & 1);
        attn_merge_kernel<<<NGRAPH, 256>>>();
    }
    gemm_fc_kernel<<<gFc, 256>>>(fc_w, fc_b, out);
}

// round 10
// speedup vs baseline: 2.6445x; 1.4245x over previous
#include <cuda_runtime.h>
#include <cuda_fp16.h>
#include <math_constants.h>
#include <cstdint>

typedef unsigned int u32;

#define NGRAPH 1024
#define D      256
#define NITERS 6
#define NSPLIT 4
#define MAXN   400000

// ---------------- device scratch ----------------
__device__ __align__(16) float g_h[NGRAPH * D];
__device__ __align__(16) float g_read[NGRAPH * D];
__device__ __align__(16) float g_c[2][NGRAPH * D];            // ping-pong
__device__ __align__(16) float g_gates[NGRAPH * 4 * D];
__device__ __align__(16) __half g_x16[NGRAPH * 2 * D];        // [1024][512] = [h | read] fp16
__device__ __align__(16) __half g_W16[4 * D * 2 * D];         // [1024][512] = [Wc | Wr] fp16
__device__ __align__(16) float g_pm[NGRAPH * NSPLIT];
__device__ __align__(16) float g_ps[NGRAPH * NSPLIT];
__device__ __align__(16) float g_pr[NGRAPH * NSPLIT * D];
__device__ __align__(16) __half g_feat16[(size_t)MAXN * D];   // fp16 feat copy
__device__ int g_segoff[NGRAPH + 1];

// ---------------- helpers ----------------
__device__ __forceinline__ u32 smem_u32(const void* p) {
    return (u32)__cvta_generic_to_shared(p);
}

__device__ __forceinline__ void ldsm4(u32* r, u32 addr) {
    asm volatile("ldmatrix.sync.aligned.m8n8.x4.shared.b16 {%0,%1,%2,%3}, [%4];"
        : "=r"(r[0]), "=r"(r[1]), "=r"(r[2]), "=r"(r[3]) : "r"(addr));
}

__device__ __forceinline__ void mma16816(float* c, const u32* a, u32 b0, u32 b1) {
    asm volatile(
        "mma.sync.aligned.m16n8k16.row.col.f32.f16.f16.f32 "
        "{%0,%1,%2,%3}, {%4,%5,%6,%7}, {%8,%9}, {%0,%1,%2,%3};"
        : "+f"(c[0]), "+f"(c[1]), "+f"(c[2]), "+f"(c[3])
        : "r"(a[0]), "r"(a[1]), "r"(a[2]), "r"(a[3]), "r"(b0), "r"(b1));
}

__device__ __forceinline__ void unpack8(uint4 v, float* f) {
    float2 t0 = __half22float2(*(__half2*)&v.x);
    float2 t1 = __half22float2(*(__half2*)&v.y);
    float2 t2 = __half22float2(*(__half2*)&v.z);
    float2 t3 = __half22float2(*(__half2*)&v.w);
    f[0] = t0.x; f[1] = t0.y; f[2] = t1.x; f[3] = t1.y;
    f[4] = t2.x; f[5] = t2.y; f[6] = t3.x; f[7] = t3.y;
}

// ---------------- segment offsets ----------------
__global__ void seg_offsets_kernel(const int* __restrict__ seg, int N) {
    int b = blockIdx.x * blockDim.x + threadIdx.x;
    if (b > NGRAPH) return;
    int lo = 0, hi = N;
    while (lo < hi) {
        int mid = (lo + hi) >> 1;
        if (seg[mid] < b) lo = mid + 1; else hi = mid;
    }
    g_segoff[b] = lo;
}

__global__ void init_zero_kernel() {
    int i = blockIdx.x * blockDim.x + threadIdx.x;
    if (i < NGRAPH * D) { g_h[i] = 0.f; g_read[i] = 0.f; g_c[0][i] = 0.f; }
    if (i < NGRAPH * 2 * D) g_x16[i] = __float2half(0.f);
}

// W16[n][k] = W_ih[n][k] + (k < 256 ? W_hh[n][k] : 0), fp16
__global__ void prep_w16_kernel(const float* __restrict__ W_ih,
                                const float* __restrict__ W_hh) {
    int i = blockIdx.x * blockDim.x + threadIdx.x;
    if (i >= 4 * D * 2 * D) return;
    int n = i >> 9;
    int k = i & 511;
    float v = W_ih[(size_t)n * 2 * D + k];
    if (k < D) v += W_hh[(size_t)n * D + k];
    g_W16[i] = __float2half(v);
}

// ---------------- tensor-core gates GEMM ----------------
// gates[1024,1024] = X16[1024,512] @ W16[1024,512]^T + (b1 + b2)
// BM=64, BN=128, BK=32, 256 threads (8 warps: 2x4), grid (8,16) = 128 blocks.
__global__ void __launch_bounds__(256)
gemm_gates_mma_kernel(const float* __restrict__ b1, const float* __restrict__ b2)
{
    const int PAD = 40;     // halves per padded row (80B stride, conflict-free)
    __shared__ __half As[2][64][PAD];
    __shared__ __half Bs[2][128][PAD];

    int tid = threadIdx.x;
    int warp = tid >> 5;
    int lane = tid & 31;
    int wm = warp >> 2;       // 0..1
    int wn = warp & 3;        // 0..3
    int row0 = blockIdx.y * 64;
    int col0 = blockIdx.x * 128;

    float acc[2][4][4];
#pragma unroll
    for (int i = 0; i < 2; i++) {
#pragma unroll
        for (int j = 0; j < 4; j++) {
#pragma unroll
            for (int k = 0; k < 4; k++) { acc[i][j][k] = 0.f; }
        }
    }

    int arow = tid >> 2;
    int acol = (tid & 3) * 8;

    int a_r = lane & 15;
    int a_c = (lane >> 4) * 8;
    int b_rr = lane & 7;
    int b_sel = lane >> 3;
    int b_rowoff = (b_sel >> 1) * 8 + b_rr;
    int b_coloff = (b_sel & 1) * 8;

    uint4 va, vb0, vb1;
    va  = *(const uint4*)(g_x16 + (size_t)(row0 + arow) * 512 + acol);
    vb0 = *(const uint4*)(g_W16 + (size_t)(col0 + arow) * 512 + acol);
    vb1 = *(const uint4*)(g_W16 + (size_t)(col0 + arow + 64) * 512 + acol);
    *(uint4*)&As[0][arow][acol] = va;
    *(uint4*)&Bs[0][arow][acol] = vb0;
    *(uint4*)&Bs[0][arow + 64][acol] = vb1;
    __syncthreads();

    for (int t = 0; t < 16; t++) {
        if (t + 1 < 16) {
            int kk = (t + 1) * 32 + acol;
            va  = *(const uint4*)(g_x16 + (size_t)(row0 + arow) * 512 + kk);
            vb0 = *(const uint4*)(g_W16 + (size_t)(col0 + arow) * 512 + kk);
            vb1 = *(const uint4*)(g_W16 + (size_t)(col0 + arow + 64) * 512 + kk);
        }
        int cur = t & 1;
#pragma unroll
        for (int ks = 0; ks < 2; ks++) {
            u32 afrag[2][4];
            u32 bfrag[2][4];
#pragma unroll
            for (int mt = 0; mt < 2; mt++) {
                u32 addr = smem_u32(&As[cur][wm * 32 + mt * 16 + a_r][ks * 16 + a_c]);
                ldsm4(afrag[mt], addr);
            }
#pragma unroll
            for (int g = 0; g < 2; g++) {
                u32 addr = smem_u32(&Bs[cur][wn * 32 + g * 16 + b_rowoff][ks * 16 + b_coloff]);
                ldsm4(bfrag[g], addr);
            }
#pragma unroll
            for (int mt = 0; mt < 2; mt++) {
#pragma unroll
                for (int g = 0; g < 2; g++) {
                    mma16816(acc[mt][g * 2 + 0], afrag[mt], bfrag[g][0], bfrag[g][1]);
                    mma16816(acc[mt][g * 2 + 1], afrag[mt], bfrag[g][2], bfrag[g][3]);
                }
            }
        }
        if (t + 1 < 16) {
            *(uint4*)&As[cur ^ 1][arow][acol] = va;
            *(uint4*)&Bs[cur ^ 1][arow][acol] = vb0;
            *(uint4*)&Bs[cur ^ 1][arow + 64][acol] = vb1;
        }
        __syncthreads();
    }

    int trow = lane >> 2;
    int tcol = (lane & 3) * 2;
#pragma unroll
    for (int mt = 0; mt < 2; mt++) {
#pragma unroll
        for (int nt = 0; nt < 4; nt++) {
            int col = col0 + wn * 32 + nt * 8 + tcol;
            float bb0 = b1[col] + b2[col];
            float bb1 = b1[col + 1] + b2[col + 1];
            int r0 = row0 + wm * 32 + mt * 16 + trow;
            float2* p0 = (float2*)(g_gates + (size_t)r0 * 4 * D + col);
            float2* p1 = (float2*)(g_gates + (size_t)(r0 + 8) * 4 * D + col);
            *p0 = make_float2(acc[mt][nt][0] + bb0, acc[mt][nt][1] + bb1);
            *p1 = make_float2(acc[mt][nt][2] + bb0, acc[mt][nt][3] + bb1);
        }
    }
}

// ---------------- fp32 fc GEMM (runs once) ----------------
__global__ void __launch_bounds__(256)
gemm_fc_kernel(const float* __restrict__ fc_w, const float* __restrict__ fc_b,
               float* __restrict__ out)
{
    const int BK = 16, T = 32;
    __shared__ float As[2][BK][64];
    __shared__ float Bs[2][BK][64];

    int tid = threadIdx.x;
    int tx = tid & 15;
    int ty = tid >> 4;
    int row0 = blockIdx.y * 64;
    int col0 = blockIdx.x * 64;
    int lr = tid >> 2;
    int lc = (tid & 3) * 4;

    float acc[4][4];
#pragma unroll
    for (int i = 0; i < 4; i++) {
#pragma unroll
        for (int j = 0; j < 4; j++) { acc[i][j] = 0.f; }
    }

    float4 av, bv;
    av = *(const float4*)(g_h + (size_t)(row0 + lr) * D + lc);
    bv = *(const float4*)(fc_w + (size_t)(col0 + lr) * 2 * D + lc);
    As[0][lc + 0][lr] = av.x; As[0][lc + 1][lr] = av.y;
    As[0][lc + 2][lr] = av.z; As[0][lc + 3][lr] = av.w;
    Bs[0][lc + 0][lr] = bv.x; Bs[0][lc + 1][lr] = bv.y;
    Bs[0][lc + 2][lr] = bv.z; Bs[0][lc + 3][lr] = bv.w;
    __syncthreads();

    for (int t = 0; t < T; t++) {
        if (t + 1 < T) {
            int kk = (t + 1) * BK + lc;
            const float* A = (kk < D) ? g_h : g_read;
            int k2 = (kk < D) ? kk : kk - D;
            av = *(const float4*)(A + (size_t)(row0 + lr) * D + k2);
            bv = *(const float4*)(fc_w + (size_t)(col0 + lr) * 2 * D + kk);
        }
        int cur = t & 1;
#pragma unroll
        for (int k = 0; k < BK; k++) {
            float a[4], b[4];
#pragma unroll
            for (int i = 0; i < 4; i++) { a[i] = As[cur][k][ty * 4 + i]; }
#pragma unroll
            for (int j = 0; j < 4; j++) { b[j] = Bs[cur][k][tx * 4 + j]; }
#pragma unroll
            for (int i = 0; i < 4; i++) {
#pragma unroll
                for (int j = 0; j < 4; j++) { acc[i][j] += a[i] * b[j]; }
            }
        }
        if (t + 1 < T) {
            int nb = cur ^ 1;
            As[nb][lc + 0][lr] = av.x; As[nb][lc + 1][lr] = av.y;
            As[nb][lc + 2][lr] = av.z; As[nb][lc + 3][lr] = av.w;
            Bs[nb][lc + 0][lr] = bv.x; Bs[nb][lc + 1][lr] = bv.y;
            Bs[nb][lc + 2][lr] = bv.z; Bs[nb][lc + 3][lr] = bv.w;
        }
        __syncthreads();
    }

#pragma unroll
    for (int j = 0; j < 4; j++) {
        int col = col0 + tx * 4 + j;
        float bias = fc_b[col];
#pragma unroll
        for (int i = 0; i < 4; i++) {
            int row = row0 + ty * 4 + i;
            out[(size_t)row * D + col] = acc[i][j] + bias;
        }
    }
}

// ---------------- shared LSTM-elementwise helper ----------------
__device__ __forceinline__ void lstm_elem(int b, int parity, float* q_sm) {
    const float* g = g_gates + (size_t)b * 4 * D;
    int d = threadIdx.x;
    float gi = g[d];
    float gf = g[D + d];
    float gg = g[2 * D + d];
    float go = g[3 * D + d];
    float si = 1.f / (1.f + __expf(-gi));
    float sf = 1.f / (1.f + __expf(-gf));
    float so = 1.f / (1.f + __expf(-go));
    float c = sf * g_c[parity][(size_t)b * D + d] + si * tanhf(gg);
    float h = so * tanhf(c);
    g_c[parity ^ 1][(size_t)b * D + d] = c;
    g_h[(size_t)b * D + d] = h;                       // fp32 (fc GEMM)
    g_x16[(size_t)b * 2 * D + d] = __float2half(h);   // fp16 (gates GEMM)
    q_sm[d] = h;
}

// ---------------- iter-1: fp32 attention + fp16 conversion write ----------------
__global__ void __launch_bounds__(256)
attn_phase1_f32_kernel(const float* __restrict__ feat, int parity)
{
    int u = blockIdx.x;
    int b = u >> 2;
    int sp = u & 3;
    int tid = threadIdx.x;
    int w = tid >> 5;
    int lane = tid & 31;

    __shared__ float q_sm[D];
    lstm_elem(b, parity, q_sm);
    __syncthreads();

    int start = g_segoff[b];
    int end = g_segoff[b + 1];

    float4 qa = *(const float4*)(q_sm + lane * 4);
    float4 qb = *(const float4*)(q_sm + 128 + lane * 4);

    float m = -CUDART_INF_F, s = 0.f;
    float4 ra = make_float4(0.f, 0.f, 0.f, 0.f);
    float4 rb = make_float4(0.f, 0.f, 0.f, 0.f);

    for (int n = start + sp * 8 + w; n < end; n += 32) {
        const float4* fp = (const float4*)(feat + (size_t)n * D);
        float4 fa = fp[lane];
        float4 fb = fp[32 + lane];

        __half* row16 = g_feat16 + (size_t)n * D;
        ((__half2*)row16)[lane * 2 + 0] = __float22half2_rn(make_float2(fa.x, fa.y));
        ((__half2*)row16)[lane * 2 + 1] = __float22half2_rn(make_float2(fa.z, fa.w));
        ((__half2*)(row16 + 128))[lane * 2 + 0] = __float22half2_rn(make_float2(fb.x, fb.y));
        ((__half2*)(row16 + 128))[lane * 2 + 1] = __float22half2_rn(make_float2(fb.z, fb.w));

        float p = fa.x * qa.x + fa.y * qa.y + fa.z * qa.z + fa.w * qa.w
                + fb.x * qb.x + fb.y * qb.y + fb.z * qb.z + fb.w * qb.w;
#pragma unroll
        for (int o = 16; o; o >>= 1) { p += __shfl_xor_sync(0xffffffffu, p, o); }

        float wgt;
        if (p > m) {
            float sc = __expf(m - p);   // first node: exp(-inf) = +0
            s *= sc;
            ra.x *= sc; ra.y *= sc; ra.z *= sc; ra.w *= sc;
            rb.x *= sc; rb.y *= sc; rb.z *= sc; rb.w *= sc;
            m = p;
            wgt = 1.f;
        } else {
            wgt = __expf(p - m);
        }
        s += wgt;
        ra.x += wgt * fa.x; ra.y += wgt * fa.y; ra.z += wgt * fa.z; ra.w += wgt * fa.w;
        rb.x += wgt * fb.x; rb.y += wgt * fb.y; rb.z += wgt * fb.z; rb.w += wgt * fb.w;
    }

    __shared__ float sm_m[8];
    __shared__ float sm_s[8];
    __shared__ float4 sm_ra[8][32];
    __shared__ float4 sm_rb[8][32];
    if (lane == 0) { sm_m[w] = m; sm_s[w] = s; }
    sm_ra[w][lane] = ra;
    sm_rb[w][lane] = rb;
    __syncthreads();

    int d = tid;
    float M = -CUDART_INF_F;
#pragma unroll
    for (int i = 0; i < 8; i++) { M = fmaxf(M, sm_m[i]); }

    float S = 0.f, R = 0.f;
    if (M > -CUDART_INF_F) {
        const float* base;
        if (d < 128) { base = ((const float*)sm_ra) + d; }
        else         { base = ((const float*)sm_rb) + (d - 128); }
#pragma unroll
        for (int i = 0; i < 8; i++) {
            float sc = __expf(sm_m[i] - M);
            S += sm_s[i] * sc;
            R += base[i * 128] * sc;
        }
    }
    g_pr[(size_t)u * D + d] = R;
    if (tid == 0) { g_pm[u] = M; g_ps[u] = S; }
}

// ---------------- iters 2..6: fp16 attention, 2-node unroll ----------------
__global__ void __launch_bounds__(256)
attn_phase1_f16_kernel(int parity)
{
    int u = blockIdx.x;
    int b = u >> 2;
    int sp = u & 3;
    int tid = threadIdx.x;
    int w = tid >> 5;
    int lane = tid & 31;

    __shared__ float q_sm[D];
    lstm_elem(b, parity, q_sm);
    __syncthreads();

    int start = g_segoff[b];
    int end = g_segoff[b + 1];

    float qv[8];
#pragma unroll
    for (int i = 0; i < 8; i++) { qv[i] = q_sm[lane * 8 + i]; }

    float m = -CUDART_INF_F, s = 0.f;
    float r[8];
#pragma unroll
    for (int i = 0; i < 8; i++) { r[i] = 0.f; }

    int n = start + sp * 8 + w;
    for (; n + 32 < end; n += 64) {
        uint4 v0 = ((const uint4*)(g_feat16 + (size_t)n * D))[lane];
        uint4 v1 = ((const uint4*)(g_feat16 + (size_t)(n + 32) * D))[lane];
        float f0[8];
        float f1[8];
        unpack8(v0, f0);
        unpack8(v1, f1);

        float p0 = 0.f, p1 = 0.f;
#pragma unroll
        for (int i = 0; i < 8; i++) { p0 += f0[i] * qv[i]; p1 += f1[i] * qv[i]; }
#pragma unroll
        for (int o = 16; o; o >>= 1) {
            p0 += __shfl_xor_sync(0xffffffffu, p0, o);
            p1 += __shfl_xor_sync(0xffffffffu, p1, o);
        }

        float pmax = fmaxf(p0, p1);
        if (pmax > m) {
            float sc = __expf(m - pmax);   // first pair: exp(-inf) = +0
            s *= sc;
#pragma unroll
            for (int i = 0; i < 8; i++) { r[i] *= sc; }
            m = pmax;
        }
        float w0 = __expf(p0 - m);
        float w1 = __expf(p1 - m);
        s += w0 + w1;
#pragma unroll
        for (int i = 0; i < 8; i++) { r[i] += w0 * f0[i] + w1 * f1[i]; }
    }
    if (n < end) {
        uint4 v0 = ((const uint4*)(g_feat16 + (size_t)n * D))[lane];
        float f0[8];
        unpack8(v0, f0);
        float p = 0.f;
#pragma unroll
        for (int i = 0; i < 8; i++) { p += f0[i] * qv[i]; }
#pragma unroll
        for (int o = 16; o; o >>= 1) { p += __shfl_xor_sync(0xffffffffu, p, o); }
        if (p > m) {
            float sc = __expf(m - p);
            s *= sc;
#pragma unroll
            for (int i = 0; i < 8; i++) { r[i] *= sc; }
            m = p;
        }
        float w0 = __expf(p - m);
        s += w0;
#pragma unroll
        for (int i = 0; i < 8; i++) { r[i] += w0 * f0[i]; }
    }

    __shared__ float sm_m[8];
    __shared__ float sm_s[8];
    __shared__ float sm_r[8][D];
    if (lane == 0) { sm_m[w] = m; sm_s[w] = s; }
    *(float4*)&sm_r[w][lane * 8 + 0] = make_float4(r[0], r[1], r[2], r[3]);
    *(float4*)&sm_r[w][lane * 8 + 4] = make_float4(r[4], r[5], r[6], r[7]);
    __syncthreads();

    int d = tid;
    float M = -CUDART_INF_F;
#pragma unroll
    for (int i = 0; i < 8; i++) { M = fmaxf(M, sm_m[i]); }

    float S = 0.f, R = 0.f;
    if (M > -CUDART_INF_F) {
#pragma unroll
        for (int i = 0; i < 8; i++) {
            float sc = __expf(sm_m[i] - M);
            S += sm_s[i] * sc;
            R += sm_r[i][d] * sc;
        }
    }
    g_pr[(size_t)u * D + d] = R;
    if (tid == 0) { g_pm[u] = M; g_ps[u] = S; }
}

// ---------------- merge 4 partials per graph ----------------
__global__ void __launch_bounds__(256)
attn_merge_kernel()
{
    int b = blockIdx.x;
    int d = threadIdx.x;
    float m0 = g_pm[b * 4 + 0];
    float m1 = g_pm[b * 4 + 1];
    float m2 = g_pm[b * 4 + 2];
    float m3 = g_pm[b * 4 + 3];
    float M = fmaxf(fmaxf(m0, m1), fmaxf(m2, m3));
    float out = 0.f;
    if (M > -CUDART_INF_F) {
        float e0 = __expf(m0 - M);
        float e1 = __expf(m1 - M);
        float e2 = __expf(m2 - M);
        float e3 = __expf(m3 - M);
        float S = g_ps[b * 4 + 0] * e0 + g_ps[b * 4 + 1] * e1
                + g_ps[b * 4 + 2] * e2 + g_ps[b * 4 + 3] * e3;
        float R = g_pr[(size_t)(b * 4 + 0) * D + d] * e0
                + g_pr[(size_t)(b * 4 + 1) * D + d] * e1
                + g_pr[(size_t)(b * 4 + 2) * D + d] * e2
                + g_pr[(size_t)(b * 4 + 3) * D + d] * e3;
        if (S > 0.f) { out = R / S; }
    }
    g_read[(size_t)b * D + d] = out;                          // fp32 (fc GEMM)
    g_x16[(size_t)b * 2 * D + D + d] = __float2half(out);     // fp16 (gates GEMM)
}

// ---------------- launch ----------------
extern "C" void kernel_launch(void* const* d_in, const int* in_sizes, int n_in,
                              void* d_out, int out_size)
{
    const float* feat = 0;
    const float* W_ih = 0;
    const float* W_hh = 0;
    const float* fc_w = 0;
    const float* fc_b = 0;
    const float* b_1 = 0;
    const float* b_2 = 0;
    const int* seg = 0;

    int fi = 0;
    long long best = -1;
    for (int i = 0; i < n_in; i++) {
        if ((long long)in_sizes[i] > best) { best = in_sizes[i]; fi = i; }
    }
    feat = (const float*)d_in[fi];
    int N = in_sizes[fi] / D;

    for (int i = 0; i < n_in; i++) {
        if (i == fi) continue;
        int s = in_sizes[i];
        if      (s == 4 * D * 2 * D) { W_ih = (const float*)d_in[i]; }
        else if (s == 4 * D * D)     { W_hh = (const float*)d_in[i]; }
        else if (s == D * 2 * D)     { fc_w = (const float*)d_in[i]; }
        else if (s == 4 * D)         { if (!b_1) { b_1 = (const float*)d_in[i]; }
                                       else      { b_2 = (const float*)d_in[i]; } }
        else if (s == D)             { fc_b = (const float*)d_in[i]; }
        else if (s == N)             { seg  = (const int*)d_in[i]; }
    }
    float* out = (float*)d_out;

    seg_offsets_kernel<<<(NGRAPH + 1 + 255) / 256, 256>>>(seg, N);
    init_zero_kernel<<<(NGRAPH * 2 * D + 255) / 256, 256>>>();
    prep_w16_kernel<<<(4 * D * 2 * D + 255) / 256, 256>>>(W_ih, W_hh);

    dim3 gGates(1024 / 128, 1024 / 64);   // (8, 16) = 128 blocks
    dim3 gFc(D / 64, NGRAPH / 64);        // (4, 16)

    for (int it = 0; it < NITERS; it++) {
        gemm_gates_mma_kernel<<<gGates, 256>>>(b_1, b_2);
        if (it == 0) {
            attn_phase1_f32_kernel<<<NGRAPH * NSPLIT, 256>>>(feat, 0);
        } else {
            attn_phase1_f16_kernel<<<NGRAPH * NSPLIT, 256>>>(it & 1);
        }
        attn_merge_kernel<<<NGRAPH, 256>>>();
    }
    gemm_fc_kernel<<<gFc, 256>>>(fc_w, fc_b, out);
}